// round 7
// baseline (speedup 1.0000x reference)
#include <cuda_runtime.h>
#include <cstdint>
#include <cstddef>

#define SEQLEN 512
#define BATCH  64
#define HID    512
#define INP    512
#define G4     2048
#define NB_REC 128
#define NT_REC 512

// ---------------- device scratch ----------------
__device__ float g_xproj[(size_t)SEQLEN * BATCH * G4];
__device__ __align__(16) float g_hbuf[2][BATCH * HID];
__device__ int   g_flags[4][32];

// ---------------- helpers ----------------
__device__ __forceinline__ void fma2(unsigned long long& d, unsigned long long a,
                                     unsigned long long b) {
    asm("fma.rn.f32x2 %0, %1, %2, %0;" : "+l"(d) : "l"(a), "l"(b));
}
__device__ __forceinline__ float f2sum(unsigned long long v) {
    float lo, hi;
    asm("mov.b64 {%0, %1}, %2;" : "=f"(lo), "=f"(hi) : "l"(v));
    return lo + hi;
}
__device__ __forceinline__ float sigf(float x) { return 1.0f / (1.0f + __expf(-x)); }
__device__ __forceinline__ float tanhf_acc(float x) {
    return 2.0f / (1.0f + __expf(-2.0f * x)) - 1.0f;
}
__device__ __forceinline__ unsigned smem_u32(const void* p) {
    unsigned a;
    asm("{ .reg .u64 t; cvta.to.shared.u64 t, %1; cvt.u32.u64 %0, t; }" : "=r"(a) : "l"(p));
    return a;
}
__device__ __forceinline__ void cp16(unsigned dst, const void* src) {
    asm volatile("cp.async.cg.shared.global [%0], [%1], 16;" :: "r"(dst), "l"(src));
}
__device__ __forceinline__ int ld_acq(const int* p) {
    int v;
    asm volatile("ld.acquire.gpu.global.s32 %0, [%1];" : "=r"(v) : "l"(p) : "memory");
    return v;
}
__device__ __forceinline__ void st_rel(int* p, int v) {
    asm volatile("st.release.gpu.global.s32 [%0], %1;" :: "l"(p), "r"(v) : "memory");
}

// =====================================================================================
// Kernel 1: x_proj = input @ W_ih^T + bias.  Round-2 tile shape + TRUE 2-stage pipeline.
// Block 0 additionally zeroes the recurrence progress flags (rec launches after).
// =====================================================================================
#define ASTRIDE 36
#define ASZ (128 * ASTRIDE)
#define BSZ (64 * ASTRIDE)

__global__ __launch_bounds__(256, 2)
void gemm_xproj(const float* __restrict__ A, const float* __restrict__ W,
                const float* __restrict__ bih, const float* __restrict__ bhh)
{
    extern __shared__ float smem[];
    float* Asm[2] = { smem,       smem + (ASZ + BSZ) };
    float* Bsm[2] = { smem + ASZ, smem + (ASZ + BSZ) + ASZ };

    const int tid = threadIdx.x;
    if (blockIdx.x == 0 && blockIdx.y == 0 && tid < 128)
        ((int*)g_flags)[tid] = 0;

    const int tm  = tid >> 4;
    const int tn  = tid & 15;
    const int m0  = blockIdx.x * 128;
    const int n0  = blockIdx.y * 64;

    auto copy_tile = [&](int kt) {
        const int k0 = kt * 32;
        const int sel = kt & 1;
        unsigned abase = smem_u32(Asm[sel]);
        unsigned bbase = smem_u32(Bsm[sel]);
        #pragma unroll
        for (int i = 0; i < 4; i++) {
            int idx = tid + i * 256;
            int r = idx >> 3, c = (idx & 7) * 4;
            cp16(abase + (r * ASTRIDE + c) * 4, &A[(size_t)(m0 + r) * INP + k0 + c]);
        }
        #pragma unroll
        for (int i = 0; i < 2; i++) {
            int idx = tid + i * 256;
            int r = idx >> 3, c = (idx & 7) * 4;
            cp16(bbase + (r * ASTRIDE + c) * 4, &W[(size_t)(n0 + r) * INP + k0 + c]);
        }
        asm volatile("cp.async.commit_group;");
    };

    unsigned long long acc[8][4];
    #pragma unroll
    for (int i = 0; i < 8; i++)
        #pragma unroll
        for (int j = 0; j < 4; j++) acc[i][j] = 0ull;

    copy_tile(0);
    copy_tile(1);

    for (int kt = 0; kt < 16; kt++) {
        if (kt < 15) asm volatile("cp.async.wait_group 1;" ::: "memory");
        else         asm volatile("cp.async.wait_group 0;" ::: "memory");
        __syncthreads();

        const float* As = Asm[kt & 1];
        const float* Bs = Bsm[kt & 1];
        #pragma unroll
        for (int kp = 0; kp < 16; kp++) {
            unsigned long long av[8], bv[4];
            #pragma unroll
            for (int i = 0; i < 8; i++)
                av[i] = *(const unsigned long long*)&As[(tm * 8 + i) * ASTRIDE + kp * 2];
            #pragma unroll
            for (int j = 0; j < 4; j++)
                bv[j] = *(const unsigned long long*)&Bs[(tn + j * 16) * ASTRIDE + kp * 2];
            #pragma unroll
            for (int i = 0; i < 8; i++)
                #pragma unroll
                for (int j = 0; j < 4; j++) fma2(acc[i][j], av[i], bv[j]);
        }
        __syncthreads();
        if (kt + 2 < 16) copy_tile(kt + 2);
    }

    #pragma unroll
    for (int j = 0; j < 4; j++) {
        int n = n0 + tn + j * 16;
        float bias = bih[n] + bhh[n];
        #pragma unroll
        for (int i = 0; i < 8; i++)
            g_xproj[(size_t)(m0 + tm * 8 + i) * G4 + n] = f2sum(acc[i][j]) + bias;
    }
}

// =====================================================================================
// Kernel 2: persistent recurrence — round-6 structure (512 thr, 16 k-groups),
// release/acquire flag protocol, out stores deferred past the publish.
// =====================================================================================
struct RecSmem {
    float Wsm[64][514];       // 131584 B
    float hs[16][516];        //  33024 B
    float red[16][16][66];    //  67584 B  => 232192 B
};

__global__ __launch_bounds__(NT_REC, 1)
void lstm_rec(const float* __restrict__ h0, const float* __restrict__ c0,
              const float* __restrict__ Whh, float* __restrict__ out, int write_hc)
{
    extern __shared__ char smem_raw[];
    RecSmem* sm = (RecSmem*)smem_raw;

    const int tid  = threadIdx.x;
    const int bi   = blockIdx.x >> 5;
    const int cj   = blockIdx.x & 31;
    const int lane = tid & 31;
    const int kg   = tid >> 5;          // 0..15 warp = 32-k group (16 kp)
    const int jl   = lane & 15;
    const int b0   = (lane >> 4) * 8;

    const int cb  = (tid & 255) >> 4;
    const int cjl = tid & 15;
    const size_t hofs = (size_t)(bi * 16 + cb) * HID + cj * 16 + cjl;

    for (int i = tid; i < 64 * 256; i += NT_REC) {
        int r = i >> 8;
        int kp2 = (i & 255) * 2;
        int ty = r >> 4, j = r & 15;
        *(float2*)&sm->Wsm[r][kp2] =
            *(const float2*)&Whh[(size_t)(ty * HID + cj * 16 + j) * HID + kp2];
    }
    float creg = (tid < 256) ? c0[hofs] : 0.0f;
    __syncthreads();

    int* flags = &g_flags[bi][0];

    for (int t = 0; t < SEQLEN; t++) {
        // prefetch x_proj gates (independent of h_t)
        float xg0 = 0.f, xg1 = 0.f, xg2 = 0.f, xg3 = 0.f;
        if (tid < 256) {
            size_t xofs = ((size_t)t * BATCH + bi * 16 + cb) * G4 + cj * 16 + cjl;
            xg0 = __ldcg(&g_xproj[xofs]);
            xg1 = __ldcg(&g_xproj[xofs + HID]);
            xg2 = __ldcg(&g_xproj[xofs + 2 * HID]);
            xg3 = __ldcg(&g_xproj[xofs + 3 * HID]);
        }

        // wait for h_t producers (32 blocks of this bi group)
        if (t > 0 && tid < 32) { while (ld_acq(&flags[tid]) < t) { } }
        __syncthreads();

        // stage h_t
        const float* hsrc = (t == 0) ? h0 : g_hbuf[t & 1];
        const float* hrow = hsrc + (size_t)(bi * 16) * HID;
        #pragma unroll
        for (int u = 0; u < 4; u++) {
            int i = tid + u * NT_REC;
            int b = i >> 7;
            int c4 = (i & 127) * 4;
            float4 v = __ldcg((const float4*)(hrow + (size_t)b * HID + c4));
            *(float4*)&sm->hs[b][c4] = v;
        }
        __syncthreads();

        // partial gates over this warp's 32-k range
        unsigned long long acc[8][4];
        #pragma unroll
        for (int i = 0; i < 8; i++)
            #pragma unroll
            for (int j = 0; j < 4; j++) acc[i][j] = 0ull;

        const int kp0 = kg * 16;
        #pragma unroll
        for (int kp = kp0; kp < kp0 + 16; kp++) {
            unsigned long long wv[4], hv[8];
            #pragma unroll
            for (int ty = 0; ty < 4; ty++)
                wv[ty] = *(const unsigned long long*)&sm->Wsm[ty * 16 + jl][kp * 2];
            #pragma unroll
            for (int i = 0; i < 8; i++)
                hv[i] = *(const unsigned long long*)&sm->hs[b0 + i][kp * 2];
            #pragma unroll
            for (int i = 0; i < 8; i++)
                #pragma unroll
                for (int ty = 0; ty < 4; ty++) fma2(acc[i][ty], hv[i], wv[ty]);
        }
        #pragma unroll
        for (int i = 0; i < 8; i++) {
            float2 v0, v1;
            v0.x = f2sum(acc[i][0]); v0.y = f2sum(acc[i][1]);
            v1.x = f2sum(acc[i][2]); v1.y = f2sum(acc[i][3]);
            float* dst = &sm->red[kg][jl][(b0 + i) * 4];
            *(float2*)dst = v0;
            *(float2*)(dst + 2) = v1;
        }
        __syncthreads();

        // reduce + elementwise; publish h FIRST, defer out stores past the flag
        float hn = 0.f;
        if (tid < 256) {
            float s0, s1, s2, s3;
            {
                const float* rp = &sm->red[0][cjl][cb * 4];
                float2 a = *(const float2*)rp;
                float2 b = *(const float2*)(rp + 2);
                s0 = a.x; s1 = a.y; s2 = b.x; s3 = b.y;
            }
            #pragma unroll
            for (int kk = 1; kk < 16; kk++) {
                const float* rp = &sm->red[kk][cjl][cb * 4];
                float2 a = *(const float2*)rp;
                float2 b = *(const float2*)(rp + 2);
                s0 += a.x; s1 += a.y; s2 += b.x; s3 += b.y;
            }
            float iv = sigf(s0 + xg0);
            float fv = sigf(s1 + xg1);
            float gv = tanhf_acc(s2 + xg2);
            float ov = sigf(s3 + xg3);
            creg = fv * creg + iv * gv;
            hn = ov * tanhf_acc(creg);
            g_hbuf[(t + 1) & 1][hofs] = hn;          // the only store the release must cover
        }

        __syncthreads();                              // all g_hbuf writes happen-before
        if (tid == 0) st_rel(&g_flags[bi][cj], t + 1);

        if (tid < 256) {
            out[(size_t)t * (BATCH * HID) + hofs] = hn;   // off the critical path
            if (write_hc && t == SEQLEN - 1) {
                out[(size_t)SEQLEN * BATCH * HID + hofs] = hn;
                out[(size_t)SEQLEN * BATCH * HID + BATCH * HID + hofs] = creg;
            }
        }
    }
}

// =====================================================================================
extern "C" void kernel_launch(void* const* d_in, const int* in_sizes, int n_in,
                              void* d_out, int out_size)
{
    const float* input = (const float*)d_in[0];
    const float* h0    = (const float*)d_in[1];
    const float* c0    = (const float*)d_in[2];
    const float* Wih   = (const float*)d_in[3];
    const float* Whh   = (const float*)d_in[4];
    const float* bih   = (const float*)d_in[5];
    const float* bhh   = (const float*)d_in[6];
    (void)in_sizes; (void)n_in;

    float* out = (float*)d_out;
    const int n_outputs = SEQLEN * BATCH * HID;
    int write_hc = (out_size >= n_outputs + 2 * BATCH * HID) ? 1 : 0;

    static int configured = 0;
    const int gemm_smem = 2 * (ASZ + BSZ) * (int)sizeof(float);
    if (!configured) {
        cudaFuncSetAttribute(gemm_xproj, cudaFuncAttributeMaxDynamicSharedMemorySize,
                             gemm_smem);
        cudaFuncSetAttribute(lstm_rec, cudaFuncAttributeMaxDynamicSharedMemorySize,
                             (int)sizeof(RecSmem));
        configured = 1;
    }

    gemm_xproj<<<dim3((SEQLEN * BATCH) / 128, G4 / 64), 256, gemm_smem>>>(
        input, Wih, bih, bhh);
    lstm_rec<<<NB_REC, NT_REC, sizeof(RecSmem)>>>(h0, c0, Whh, out, write_hc);
}

// round 8
// speedup vs baseline: 1.3570x; 1.3570x over previous
#include <cuda_runtime.h>
#include <cuda_bf16.h>
#include <cstdint>
#include <cstddef>

#define SEQLEN 512
#define BATCH  64
#define HID    512
#define INP    512
#define G4     2048
#define NB_REC 128
#define NT_REC 512
#define MTOT   (SEQLEN * BATCH)

// ---------------- device scratch ----------------
__device__ float g_xproj[(size_t)SEQLEN * BATCH * G4];
__device__ __align__(16) float g_hbuf[2][BATCH * HID];
__device__ int   g_flags[4][32];
__device__ __align__(256) __nv_bfloat16 g_Ah[(size_t)MTOT * INP];
__device__ __align__(256) __nv_bfloat16 g_Al[(size_t)MTOT * INP];
__device__ __align__(256) __nv_bfloat16 g_Wh[(size_t)G4 * INP];
__device__ __align__(256) __nv_bfloat16 g_Wl[(size_t)G4 * INP];

// ---------------- helpers ----------------
__device__ __forceinline__ void fma2(unsigned long long& d, unsigned long long a,
                                     unsigned long long b) {
    asm("fma.rn.f32x2 %0, %1, %2, %0;" : "+l"(d) : "l"(a), "l"(b));
}
__device__ __forceinline__ float f2sum(unsigned long long v) {
    float lo, hi;
    asm("mov.b64 {%0, %1}, %2;" : "=f"(lo), "=f"(hi) : "l"(v));
    return lo + hi;
}
__device__ __forceinline__ float sigf(float x) { return 1.0f / (1.0f + __expf(-x)); }
__device__ __forceinline__ float tanhf_acc(float x) {
    return 2.0f / (1.0f + __expf(-2.0f * x)) - 1.0f;
}
__device__ __forceinline__ unsigned smem_u32(const void* p) {
    unsigned a;
    asm("{ .reg .u64 t; cvta.to.shared.u64 t, %1; cvt.u32.u64 %0, t; }" : "=r"(a) : "l"(p));
    return a;
}
__device__ __forceinline__ void cp16(unsigned dst, const void* src) {
    asm volatile("cp.async.cg.shared.global [%0], [%1], 16;" :: "r"(dst), "l"(src));
}
__device__ __forceinline__ unsigned lds32(unsigned addr) {
    unsigned v;
    asm("ld.shared.b32 %0, [%1];" : "=r"(v) : "r"(addr));
    return v;
}
__device__ __forceinline__ void mma_bf16(float* d, const unsigned* a, const unsigned* b) {
    asm("mma.sync.aligned.m16n8k16.row.col.f32.bf16.bf16.f32 "
        "{%0,%1,%2,%3}, {%4,%5,%6,%7}, {%8,%9}, {%0,%1,%2,%3};"
        : "+f"(d[0]), "+f"(d[1]), "+f"(d[2]), "+f"(d[3])
        : "r"(a[0]), "r"(a[1]), "r"(a[2]), "r"(a[3]), "r"(b[0]), "r"(b[1]));
}

// =====================================================================================
// fp32 -> bf16 hi/lo split. Block 0 also zeroes recurrence flags.
// =====================================================================================
__global__ void conv_split(const float* __restrict__ src, __nv_bfloat16* __restrict__ hi,
                           __nv_bfloat16* __restrict__ lo, int n4)
{
    if (blockIdx.x == 0 && threadIdx.x < 128) ((int*)g_flags)[threadIdx.x] = 0;
    int i = blockIdx.x * blockDim.x + threadIdx.x;
    int stride = gridDim.x * blockDim.x;
    for (; i < n4; i += stride) {
        float4 v = ((const float4*)src)[i];
        float f[4] = {v.x, v.y, v.z, v.w};
        unsigned hv0 = 0, hv1 = 0, lv0 = 0, lv1 = 0;
        #pragma unroll
        for (int j = 0; j < 4; j++) {
            __nv_bfloat16 h = __float2bfloat16(f[j]);
            __nv_bfloat16 l = __float2bfloat16(f[j] - __bfloat162float(h));
            unsigned hb = (unsigned)__bfloat16_as_ushort(h);
            unsigned lb = (unsigned)__bfloat16_as_ushort(l);
            if (j < 2) { hv0 |= hb << (16 * j);       lv0 |= lb << (16 * j); }
            else       { hv1 |= hb << (16 * (j - 2)); lv1 |= lb << (16 * (j - 2)); }
        }
        uint2 hh; hh.x = hv0; hh.y = hv1;
        uint2 ll; ll.x = lv0; ll.y = lv1;
        ((uint2*)hi)[i] = hh;
        ((uint2*)lo)[i] = ll;
    }
}

// =====================================================================================
// Kernel 1: xproj GEMM via mma.sync bf16 split. CTA 128M x 64N, 8 warps (4m x 2n),
// warp tile 32x32, KT=32 (2 x k16), 2-stage cp.async. Rows stored with 80B stride
// (16B pad) => fragment LDS.32 banks g*20+t are all-distinct (conflict-free).
// =====================================================================================
#define KT 32
#define APLANE 10240      // 128 rows * 80B
#define BPLANE 5120       // 64 rows * 80B
#define STG_SZ (2 * APLANE + 2 * BPLANE)   // 30720
#define GEMM_SMEM (2 * STG_SZ)

__global__ __launch_bounds__(256, 2)
void gemm_hmma(const float* __restrict__ bih, const float* __restrict__ bhh)
{
    extern __shared__ char smraw[];
    const unsigned SB = smem_u32(smraw);
    const int tid  = threadIdx.x;
    const int lane = tid & 31;
    const int wid  = tid >> 5;
    const int wm   = wid >> 1;          // 0..3 -> m offset wm*32
    const int wn   = wid & 1;           // 0..1 -> n offset wn*32
    const int g    = lane >> 2;         // fragment group row 0..7
    const int t    = lane & 3;          // fragment col pair 0..3
    const int n0   = blockIdx.x * 64;
    const int m0   = blockIdx.y * 128;

    auto copy_tile = [&](int kt) {
        const unsigned sb = SB + (unsigned)(kt & 1) * STG_SZ;
        const int k0 = kt * KT;
        #pragma unroll
        for (int u = 0; u < 4; u++) {           // A hi/lo: 1024 chunks
            int idx = tid + u * 256;
            int plane = idx >> 9, r = (idx >> 2) & 127, ch = idx & 3;
            const __nv_bfloat16* src = (plane ? g_Al : g_Ah)
                                     + (size_t)(m0 + r) * INP + k0 + ch * 8;
            cp16(sb + (unsigned)(plane * APLANE + r * 80 + ch * 16), src);
        }
        #pragma unroll
        for (int u = 0; u < 2; u++) {           // B hi/lo: 512 chunks
            int idx = tid + u * 256;
            int plane = (idx >> 8) & 1, r = (idx >> 2) & 63, ch = idx & 3;
            const __nv_bfloat16* src = (plane ? g_Wl : g_Wh)
                                     + (size_t)(n0 + r) * INP + k0 + ch * 8;
            cp16(sb + (unsigned)(2 * APLANE + plane * BPLANE + r * 80 + ch * 16), src);
        }
        asm volatile("cp.async.commit_group;");
    };

    float d[2][4][4];
    #pragma unroll
    for (int i = 0; i < 2; i++)
        #pragma unroll
        for (int j = 0; j < 4; j++)
            #pragma unroll
            for (int q = 0; q < 4; q++) d[i][j][q] = 0.f;

    copy_tile(0);
    copy_tile(1);

    for (int kt = 0; kt < 16; kt++) {
        if (kt < 15) asm volatile("cp.async.wait_group 1;" ::: "memory");
        else         asm volatile("cp.async.wait_group 0;" ::: "memory");
        __syncthreads();

        const unsigned sb = SB + (unsigned)(kt & 1) * STG_SZ;
        #pragma unroll
        for (int sub = 0; sub < 2; sub++) {
            const unsigned koff = (unsigned)(sub * 32 + t * 4);
            unsigned ah[2][4], al[2][4], bh[4][2], bl[4][2];
            #pragma unroll
            for (int i = 0; i < 2; i++) {
                unsigned b0 = sb + (unsigned)((wm * 32 + i * 16 + g) * 80) + koff;
                ah[i][0] = lds32(b0);            ah[i][2] = lds32(b0 + 16);
                ah[i][1] = lds32(b0 + 640);      ah[i][3] = lds32(b0 + 656);
                al[i][0] = lds32(b0 + APLANE);       al[i][2] = lds32(b0 + APLANE + 16);
                al[i][1] = lds32(b0 + APLANE + 640); al[i][3] = lds32(b0 + APLANE + 656);
            }
            #pragma unroll
            for (int j = 0; j < 4; j++) {
                unsigned b0 = sb + (unsigned)(2 * APLANE + (wn * 32 + j * 8 + g) * 80) + koff;
                bh[j][0] = lds32(b0);          bh[j][1] = lds32(b0 + 16);
                bl[j][0] = lds32(b0 + BPLANE); bl[j][1] = lds32(b0 + BPLANE + 16);
            }
            #pragma unroll
            for (int i = 0; i < 2; i++)
                #pragma unroll
                for (int j = 0; j < 4; j++) {
                    mma_bf16(d[i][j], ah[i], bh[j]);
                    mma_bf16(d[i][j], ah[i], bl[j]);
                    mma_bf16(d[i][j], al[i], bh[j]);
                }
        }
        __syncthreads();
        if (kt + 2 < 16) copy_tile(kt + 2);
    }

    // epilogue: d0,d1 -> (row, col..col+1); d2,d3 -> (row+8, ...)
    #pragma unroll
    for (int j = 0; j < 4; j++) {
        int col = n0 + wn * 32 + j * 8 + t * 2;
        float b0 = bih[col] + bhh[col];
        float b1 = bih[col + 1] + bhh[col + 1];
        #pragma unroll
        for (int i = 0; i < 2; i++) {
            int row = m0 + wm * 32 + i * 16 + g;
            float2 v0; v0.x = d[i][j][0] + b0; v0.y = d[i][j][1] + b1;
            float2 v1; v1.x = d[i][j][2] + b0; v1.y = d[i][j][3] + b1;
            *(float2*)&g_xproj[(size_t)row * G4 + col] = v0;
            *(float2*)&g_xproj[(size_t)(row + 8) * G4 + col] = v1;
        }
    }
}

// =====================================================================================
// Kernel 2: persistent recurrence — EXACT round-6 version (best known: 4958us)
// =====================================================================================
struct RecSmem {
    float Wsm[64][514];
    float hs[16][516];
    float red[16][16][66];
};

__global__ __launch_bounds__(NT_REC, 1)
void lstm_rec(const float* __restrict__ h0, const float* __restrict__ c0,
              const float* __restrict__ Whh, float* __restrict__ out, int write_hc)
{
    extern __shared__ char smem_raw[];
    RecSmem* sm = (RecSmem*)smem_raw;

    const int tid  = threadIdx.x;
    const int bi   = blockIdx.x >> 5;
    const int cj   = blockIdx.x & 31;
    const int lane = tid & 31;
    const int kg   = tid >> 5;
    const int jl   = lane & 15;
    const int b0   = (lane >> 4) * 8;

    const int cb  = (tid & 255) >> 4;
    const int cjl = tid & 15;
    const size_t hofs = (size_t)(bi * 16 + cb) * HID + cj * 16 + cjl;

    for (int i = tid; i < 64 * 256; i += NT_REC) {
        int r = i >> 8;
        int kp2 = (i & 255) * 2;
        int ty = r >> 4, j = r & 15;
        *(float2*)&sm->Wsm[r][kp2] =
            *(const float2*)&Whh[(size_t)(ty * HID + cj * 16 + j) * HID + kp2];
    }
    float creg = (tid < 256) ? c0[hofs] : 0.0f;
    __syncthreads();

    volatile int* flags = (volatile int*)&g_flags[bi][0];

    for (int t = 0; t < SEQLEN; t++) {
        float xg0 = 0.f, xg1 = 0.f, xg2 = 0.f, xg3 = 0.f;
        if (tid < 256) {
            size_t xofs = ((size_t)t * BATCH + bi * 16 + cb) * G4 + cj * 16 + cjl;
            xg0 = __ldcg(&g_xproj[xofs]);
            xg1 = __ldcg(&g_xproj[xofs + HID]);
            xg2 = __ldcg(&g_xproj[xofs + 2 * HID]);
            xg3 = __ldcg(&g_xproj[xofs + 3 * HID]);
        }

        if (t > 0) {
            if (tid < 32) { while (flags[tid] < t) { } }
            __threadfence();
        }
        __syncthreads();

        const float* hsrc = (t == 0) ? h0 : g_hbuf[t & 1];
        const float* hrow = hsrc + (size_t)(bi * 16) * HID;
        #pragma unroll
        for (int u = 0; u < 4; u++) {
            int i = tid + u * NT_REC;
            int b = i >> 7;
            int c4 = (i & 127) * 4;
            float4 v = __ldcg((const float4*)(hrow + (size_t)b * HID + c4));
            *(float4*)&sm->hs[b][c4] = v;
        }
        __syncthreads();

        unsigned long long acc[8][4];
        #pragma unroll
        for (int i = 0; i < 8; i++)
            #pragma unroll
            for (int j = 0; j < 4; j++) acc[i][j] = 0ull;

        const int kp0 = kg * 16;
        #pragma unroll
        for (int kp = kp0; kp < kp0 + 16; kp++) {
            unsigned long long wv[4], hv[8];
            #pragma unroll
            for (int ty = 0; ty < 4; ty++)
                wv[ty] = *(const unsigned long long*)&sm->Wsm[ty * 16 + jl][kp * 2];
            #pragma unroll
            for (int i = 0; i < 8; i++)
                hv[i] = *(const unsigned long long*)&sm->hs[b0 + i][kp * 2];
            #pragma unroll
            for (int i = 0; i < 8; i++)
                #pragma unroll
                for (int ty = 0; ty < 4; ty++) fma2(acc[i][ty], hv[i], wv[ty]);
        }
        #pragma unroll
        for (int i = 0; i < 8; i++) {
            float2 v0, v1;
            v0.x = f2sum(acc[i][0]); v0.y = f2sum(acc[i][1]);
            v1.x = f2sum(acc[i][2]); v1.y = f2sum(acc[i][3]);
            float* dst = &sm->red[kg][jl][(b0 + i) * 4];
            *(float2*)dst = v0;
            *(float2*)(dst + 2) = v1;
        }
        __syncthreads();

        if (tid < 256) {
            float s0, s1, s2, s3;
            {
                const float* rp = &sm->red[0][cjl][cb * 4];
                float2 a = *(const float2*)rp;
                float2 b = *(const float2*)(rp + 2);
                s0 = a.x; s1 = a.y; s2 = b.x; s3 = b.y;
            }
            #pragma unroll
            for (int kk = 1; kk < 16; kk++) {
                const float* rp = &sm->red[kk][cjl][cb * 4];
                float2 a = *(const float2*)rp;
                float2 b = *(const float2*)(rp + 2);
                s0 += a.x; s1 += a.y; s2 += b.x; s3 += b.y;
            }
            float iv = sigf(s0 + xg0);
            float fv = sigf(s1 + xg1);
            float gv = tanhf_acc(s2 + xg2);
            float ov = sigf(s3 + xg3);
            creg = fv * creg + iv * gv;
            float hn = ov * tanhf_acc(creg);

            g_hbuf[(t + 1) & 1][hofs] = hn;
            out[(size_t)t * (BATCH * HID) + hofs] = hn;
            if (write_hc && t == SEQLEN - 1) {
                out[(size_t)SEQLEN * BATCH * HID + hofs] = hn;
                out[(size_t)SEQLEN * BATCH * HID + BATCH * HID + hofs] = creg;
            }
        }

        __threadfence();
        __syncthreads();
        if (tid == 0) atomicExch((int*)&g_flags[bi][cj], t + 1);
    }
}

// =====================================================================================
extern "C" void kernel_launch(void* const* d_in, const int* in_sizes, int n_in,
                              void* d_out, int out_size)
{
    const float* input = (const float*)d_in[0];
    const float* h0    = (const float*)d_in[1];
    const float* c0    = (const float*)d_in[2];
    const float* Wih   = (const float*)d_in[3];
    const float* Whh   = (const float*)d_in[4];
    const float* bih   = (const float*)d_in[5];
    const float* bhh   = (const float*)d_in[6];
    (void)in_sizes; (void)n_in;

    float* out = (float*)d_out;
    const int n_outputs = SEQLEN * BATCH * HID;
    int write_hc = (out_size >= n_outputs + 2 * BATCH * HID) ? 1 : 0;

    static int configured = 0;
    if (!configured) {
        cudaFuncSetAttribute(gemm_hmma, cudaFuncAttributeMaxDynamicSharedMemorySize,
                             GEMM_SMEM);
        cudaFuncSetAttribute(lstm_rec, cudaFuncAttributeMaxDynamicSharedMemorySize,
                             (int)sizeof(RecSmem));
        configured = 1;
    }

    __nv_bfloat16 *ah, *al, *wh, *wl;
    cudaGetSymbolAddress((void**)&ah, g_Ah);
    cudaGetSymbolAddress((void**)&al, g_Al);
    cudaGetSymbolAddress((void**)&wh, g_Wh);
    cudaGetSymbolAddress((void**)&wl, g_Wl);

    conv_split<<<512, 256>>>(Wih, wh, wl, (G4 * INP) / 4);
    conv_split<<<2048, 256>>>(input, ah, al, (MTOT * INP) / 4);
    gemm_hmma<<<dim3(G4 / 64, MTOT / 128), 256, GEMM_SMEM>>>(bih, bhh);
    lstm_rec<<<NB_REC, NT_REC, sizeof(RecSmem)>>>(h0, c0, Whh, out, write_hc);
}

// round 9
// speedup vs baseline: 1.5683x; 1.1557x over previous
#include <cuda_runtime.h>
#include <cuda_bf16.h>
#include <cstdint>
#include <cstddef>

#define SEQLEN 512
#define BATCH  64
#define HID    512
#define INP    512
#define G4     2048
#define NB_REC 128
#define MTOT   (SEQLEN * BATCH)

// ---------------- device scratch ----------------
__device__ float g_xproj[(size_t)SEQLEN * BATCH * G4];
__device__ __align__(16) float g_hbuf[2][BATCH * HID];
__device__ int   g_flags[4][32];
__device__ __align__(256) __nv_bfloat16 g_Ah[(size_t)MTOT * INP];
__device__ __align__(256) __nv_bfloat16 g_Al[(size_t)MTOT * INP];
__device__ __align__(256) __nv_bfloat16 g_Wh[(size_t)G4 * INP];
__device__ __align__(256) __nv_bfloat16 g_Wl[(size_t)G4 * INP];
__device__ __align__(256) __nv_bfloat16 g_Rh[(size_t)G4 * HID];   // W_hh hi
__device__ __align__(256) __nv_bfloat16 g_Rl[(size_t)G4 * HID];   // W_hh lo

// ---------------- helpers ----------------
__device__ __forceinline__ float sigf(float x) { return 1.0f / (1.0f + __expf(-x)); }
__device__ __forceinline__ float tanhf_acc(float x) {
    return 2.0f / (1.0f + __expf(-2.0f * x)) - 1.0f;
}
__device__ __forceinline__ unsigned smem_u32(const void* p) {
    unsigned a;
    asm("{ .reg .u64 t; cvta.to.shared.u64 t, %1; cvt.u32.u64 %0, t; }" : "=r"(a) : "l"(p));
    return a;
}
__device__ __forceinline__ void cp16(unsigned dst, const void* src) {
    asm volatile("cp.async.cg.shared.global [%0], [%1], 16;" :: "r"(dst), "l"(src));
}
__device__ __forceinline__ unsigned lds32(unsigned addr) {
    unsigned v;
    asm("ld.shared.b32 %0, [%1];" : "=r"(v) : "r"(addr));
    return v;
}
__device__ __forceinline__ void mma_bf16(float* d, const unsigned* a, const unsigned* b) {
    asm("mma.sync.aligned.m16n8k16.row.col.f32.bf16.bf16.f32 "
        "{%0,%1,%2,%3}, {%4,%5,%6,%7}, {%8,%9}, {%0,%1,%2,%3};"
        : "+f"(d[0]), "+f"(d[1]), "+f"(d[2]), "+f"(d[3])
        : "r"(a[0]), "r"(a[1]), "r"(a[2]), "r"(a[3]), "r"(b[0]), "r"(b[1]));
}

// =====================================================================================
// fp32 -> bf16 hi/lo split. Block 0 also zeroes recurrence flags.
// =====================================================================================
__global__ void conv_split(const float* __restrict__ src, __nv_bfloat16* __restrict__ hi,
                           __nv_bfloat16* __restrict__ lo, int n4)
{
    if (blockIdx.x == 0 && threadIdx.x < 128) ((int*)g_flags)[threadIdx.x] = 0;
    int i = blockIdx.x * blockDim.x + threadIdx.x;
    int stride = gridDim.x * blockDim.x;
    for (; i < n4; i += stride) {
        float4 v = ((const float4*)src)[i];
        float f[4] = {v.x, v.y, v.z, v.w};
        unsigned hv0 = 0, hv1 = 0, lv0 = 0, lv1 = 0;
        #pragma unroll
        for (int j = 0; j < 4; j++) {
            __nv_bfloat16 h = __float2bfloat16(f[j]);
            __nv_bfloat16 l = __float2bfloat16(f[j] - __bfloat162float(h));
            unsigned hb = (unsigned)__bfloat16_as_ushort(h);
            unsigned lb = (unsigned)__bfloat16_as_ushort(l);
            if (j < 2) { hv0 |= hb << (16 * j);       lv0 |= lb << (16 * j); }
            else       { hv1 |= hb << (16 * (j - 2)); lv1 |= lb << (16 * (j - 2)); }
        }
        uint2 hh; hh.x = hv0; hh.y = hv1;
        uint2 ll; ll.x = lv0; ll.y = lv1;
        ((uint2*)hi)[i] = hh;
        ((uint2*)lo)[i] = ll;
    }
}

// =====================================================================================
// Kernel 1: xproj GEMM via mma.sync bf16 split — EXACT round-8 version (known good)
// =====================================================================================
#define KT 32
#define APLANE 10240
#define BPLANE 5120
#define STG_SZ (2 * APLANE + 2 * BPLANE)
#define GEMM_SMEM (2 * STG_SZ)

__global__ __launch_bounds__(256, 2)
void gemm_hmma(const float* __restrict__ bih, const float* __restrict__ bhh)
{
    extern __shared__ char smraw[];
    const unsigned SB = smem_u32(smraw);
    const int tid  = threadIdx.x;
    const int lane = tid & 31;
    const int wid  = tid >> 5;
    const int wm   = wid >> 1;
    const int wn   = wid & 1;
    const int g    = lane >> 2;
    const int t    = lane & 3;
    const int n0   = blockIdx.x * 64;
    const int m0   = blockIdx.y * 128;

    auto copy_tile = [&](int kt) {
        const unsigned sb = SB + (unsigned)(kt & 1) * STG_SZ;
        const int k0 = kt * KT;
        #pragma unroll
        for (int u = 0; u < 4; u++) {
            int idx = tid + u * 256;
            int plane = idx >> 9, r = (idx >> 2) & 127, ch = idx & 3;
            const __nv_bfloat16* src = (plane ? g_Al : g_Ah)
                                     + (size_t)(m0 + r) * INP + k0 + ch * 8;
            cp16(sb + (unsigned)(plane * APLANE + r * 80 + ch * 16), src);
        }
        #pragma unroll
        for (int u = 0; u < 2; u++) {
            int idx = tid + u * 256;
            int plane = (idx >> 8) & 1, r = (idx >> 2) & 63, ch = idx & 3;
            const __nv_bfloat16* src = (plane ? g_Wl : g_Wh)
                                     + (size_t)(n0 + r) * INP + k0 + ch * 8;
            cp16(sb + (unsigned)(2 * APLANE + plane * BPLANE + r * 80 + ch * 16), src);
        }
        asm volatile("cp.async.commit_group;");
    };

    float d[2][4][4];
    #pragma unroll
    for (int i = 0; i < 2; i++)
        #pragma unroll
        for (int j = 0; j < 4; j++)
            #pragma unroll
            for (int q = 0; q < 4; q++) d[i][j][q] = 0.f;

    copy_tile(0);
    copy_tile(1);

    for (int kt = 0; kt < 16; kt++) {
        if (kt < 15) asm volatile("cp.async.wait_group 1;" ::: "memory");
        else         asm volatile("cp.async.wait_group 0;" ::: "memory");
        __syncthreads();

        const unsigned sb = SB + (unsigned)(kt & 1) * STG_SZ;
        #pragma unroll
        for (int sub = 0; sub < 2; sub++) {
            const unsigned koff = (unsigned)(sub * 32 + t * 4);
            unsigned ah[2][4], al[2][4], bh[4][2], bl[4][2];
            #pragma unroll
            for (int i = 0; i < 2; i++) {
                unsigned b0 = sb + (unsigned)((wm * 32 + i * 16 + g) * 80) + koff;
                ah[i][0] = lds32(b0);            ah[i][2] = lds32(b0 + 16);
                ah[i][1] = lds32(b0 + 640);      ah[i][3] = lds32(b0 + 656);
                al[i][0] = lds32(b0 + APLANE);       al[i][2] = lds32(b0 + APLANE + 16);
                al[i][1] = lds32(b0 + APLANE + 640); al[i][3] = lds32(b0 + APLANE + 656);
            }
            #pragma unroll
            for (int j = 0; j < 4; j++) {
                unsigned b0 = sb + (unsigned)(2 * APLANE + (wn * 32 + j * 8 + g) * 80) + koff;
                bh[j][0] = lds32(b0);          bh[j][1] = lds32(b0 + 16);
                bl[j][0] = lds32(b0 + BPLANE); bl[j][1] = lds32(b0 + BPLANE + 16);
            }
            #pragma unroll
            for (int i = 0; i < 2; i++)
                #pragma unroll
                for (int j = 0; j < 4; j++) {
                    mma_bf16(d[i][j], ah[i], bh[j]);
                    mma_bf16(d[i][j], ah[i], bl[j]);
                    mma_bf16(d[i][j], al[i], bh[j]);
                }
        }
        __syncthreads();
        if (kt + 2 < 16) copy_tile(kt + 2);
    }

    #pragma unroll
    for (int j = 0; j < 4; j++) {
        int col = n0 + wn * 32 + j * 8 + t * 2;
        float b0 = bih[col] + bhh[col];
        float b1 = bih[col + 1] + bhh[col + 1];
        #pragma unroll
        for (int i = 0; i < 2; i++) {
            int row = m0 + wm * 32 + i * 16 + g;
            float2 v0; v0.x = d[i][j][0] + b0; v0.y = d[i][j][1] + b1;
            float2 v1; v1.x = d[i][j][2] + b0; v1.y = d[i][j][3] + b1;
            *(float2*)&g_xproj[(size_t)row * G4 + col] = v0;
            *(float2*)&g_xproj[(size_t)(row + 8) * G4 + col] = v1;
        }
    }
}

// =====================================================================================
// Kernel 2: persistent recurrence with HMMA bf16-split per step.
// Block (bi,cj): 16 batch x 64 gate-rows x K=512. W_hh hi/lo resident in smem
// (kt-tiled, 80B row stride — the layout proven conflict-free in gemm_hmma).
// Each step: h -> bf16 hi/lo in smem, 16 warps = 8 n-tiles x 2 k-halves,
// 48 HMMA/warp into 3 independent accumulators, smem reduce, fp32 gate math.
// =====================================================================================
#define SM_WH  0u
#define SM_WL  81920u
#define SM_HH  163840u
#define SM_HL  184320u
#define SM_RED 204800u
#define REC_SMEM 213504

__global__ __launch_bounds__(512, 1)
void lstm_rec(const float* __restrict__ h0, const float* __restrict__ c0,
              float* __restrict__ out, int write_hc)
{
    extern __shared__ char sm[];
    const unsigned SB = smem_u32(sm);
    float* red = (float*)(sm + SM_RED);

    const int tid  = threadIdx.x;
    const int bi   = blockIdx.x >> 5;
    const int cj   = blockIdx.x & 31;
    const int lane = tid & 31;
    const int wid  = tid >> 5;
    const int nt   = wid & 7;           // n-tile (8 gate rows)
    const int kh   = wid >> 3;          // k-half (256 k)
    const int g    = lane >> 2;
    const int tq   = lane & 3;

    const int cb   = (tid & 255) >> 4;
    const int cjl  = tid & 15;
    const size_t hofs = (size_t)(bi * 16 + cb) * HID + cj * 16 + cjl;

    // ---- resident W_hh hi/lo: 64 rows x 512 k, tiled [kt][r][80B] ----
    for (int idx = tid; idx < 8192; idx += 512) {
        int plane = idx >> 12;
        int q = idx & 4095;
        int r = q >> 6, kt = (q >> 2) & 15, ch = q & 3;
        int ty = r >> 4, j = r & 15;
        const __nv_bfloat16* base = plane ? g_Rl : g_Rh;
        const __nv_bfloat16* src =
            base + (size_t)(ty * HID + cj * 16 + j) * HID + kt * 32 + ch * 8;
        cp16(SB + (plane ? SM_WL : SM_WH)
                + (unsigned)(kt * 5120 + r * 80 + ch * 16), src);
    }
    asm volatile("cp.async.commit_group;");
    asm volatile("cp.async.wait_group 0;" ::: "memory");
    float creg = (tid < 256) ? c0[hofs] : 0.0f;
    __syncthreads();

    volatile int* flags = (volatile int*)&g_flags[bi][0];

    // fragment base addresses (constant per thread)
    const unsigned aWH = SB + SM_WH + (unsigned)((nt * 8 + g) * 80 + tq * 4);
    const unsigned aWL = SB + SM_WL + (unsigned)((nt * 8 + g) * 80 + tq * 4);
    const unsigned aHH = SB + SM_HH + (unsigned)(g * 80 + tq * 4);
    const unsigned aHL = SB + SM_HL + (unsigned)(g * 80 + tq * 4);

    for (int t = 0; t < SEQLEN; t++) {
        // ---- prefetch x_proj gates ----
        float xg0 = 0.f, xg1 = 0.f, xg2 = 0.f, xg3 = 0.f;
        if (tid < 256) {
            size_t xofs = ((size_t)t * BATCH + bi * 16 + cb) * G4 + cj * 16 + cjl;
            xg0 = __ldcg(&g_xproj[xofs]);
            xg1 = __ldcg(&g_xproj[xofs + HID]);
            xg2 = __ldcg(&g_xproj[xofs + 2 * HID]);
            xg3 = __ldcg(&g_xproj[xofs + 3 * HID]);
        }

        // ---- wait for h_t producers ----
        if (t > 0) {
            if (tid < 32) { while (flags[tid] < t) { } }
            __threadfence();
        }
        __syncthreads();

        // ---- split h_t -> bf16 hi/lo smem (16 x 512; pair-packed words) ----
        const float* hrow = ((t == 0) ? h0 : g_hbuf[t & 1]) + (size_t)(bi * 16) * HID;
        #pragma unroll
        for (int u = 0; u < 8; u++) {
            int idx = tid + u * 512;
            int b = idx >> 8, p = idx & 255;
            float2 v = __ldcg((const float2*)(hrow + (size_t)b * HID + p * 2));
            __nv_bfloat16 hx = __float2bfloat16(v.x);
            __nv_bfloat16 hy = __float2bfloat16(v.y);
            float rx = v.x - __bfloat162float(hx);
            float ry = v.y - __bfloat162float(hy);
            __nv_bfloat16 lx = __float2bfloat16(rx);
            __nv_bfloat16 ly = __float2bfloat16(ry);
            unsigned hw = (unsigned)__bfloat16_as_ushort(hx)
                        | ((unsigned)__bfloat16_as_ushort(hy) << 16);
            unsigned lw = (unsigned)__bfloat16_as_ushort(lx)
                        | ((unsigned)__bfloat16_as_ushort(ly) << 16);
            unsigned off = (unsigned)((p >> 4) * 1280 + b * 80 + (p & 15) * 4);
            *(unsigned*)(sm + SM_HH + off) = hw;
            *(unsigned*)(sm + SM_HL + off) = lw;
        }
        __syncthreads();

        // ---- HMMA: warp (nt, kh): 16 k16-chunks x 3 split terms ----
        float d0[4] = {0,0,0,0}, d1[4] = {0,0,0,0}, d2[4] = {0,0,0,0};
        #pragma unroll
        for (int c = 0; c < 16; c++) {
            int k16 = kh * 16 + c;
            unsigned wo = (unsigned)((k16 >> 1) * 5120 + (k16 & 1) * 32);
            unsigned ho = (unsigned)((k16 >> 1) * 1280 + (k16 & 1) * 32);
            unsigned ah[4], al[4], bh[2], bl[2];
            ah[0] = lds32(aHH + ho);       ah[2] = lds32(aHH + ho + 16);
            ah[1] = lds32(aHH + ho + 640); ah[3] = lds32(aHH + ho + 656);
            al[0] = lds32(aHL + ho);       al[2] = lds32(aHL + ho + 16);
            al[1] = lds32(aHL + ho + 640); al[3] = lds32(aHL + ho + 656);
            bh[0] = lds32(aWH + wo);       bh[1] = lds32(aWH + wo + 16);
            bl[0] = lds32(aWL + wo);       bl[1] = lds32(aWL + wo + 16);
            mma_bf16(d0, ah, bh);
            mma_bf16(d1, ah, bl);
            mma_bf16(d2, al, bh);
        }
        // store partials: red[kh][n=64][b stride 17]
        {
            int n = nt * 8 + tq * 2;
            int base = kh * 1088 + n * 17;
            red[base + g]           = d0[0] + d1[0] + d2[0];
            red[base + 17 + g]      = d0[1] + d1[1] + d2[1];
            red[base + g + 8]       = d0[2] + d1[2] + d2[2];
            red[base + 17 + g + 8]  = d0[3] + d1[3] + d2[3];
        }
        __syncthreads();

        // ---- phase C: reduce k-halves, gates, update ----
        if (tid < 256) {
            float s0, s1, s2, s3;
            {
                int n = 0 * 16 + cjl;
                s0 = red[n * 17 + cb] + red[1088 + n * 17 + cb];
                n = 1 * 16 + cjl;
                s1 = red[n * 17 + cb] + red[1088 + n * 17 + cb];
                n = 2 * 16 + cjl;
                s2 = red[n * 17 + cb] + red[1088 + n * 17 + cb];
                n = 3 * 16 + cjl;
                s3 = red[n * 17 + cb] + red[1088 + n * 17 + cb];
            }
            float iv = sigf(s0 + xg0);
            float fv = sigf(s1 + xg1);
            float gv = tanhf_acc(s2 + xg2);
            float ov = sigf(s3 + xg3);
            creg = fv * creg + iv * gv;
            float hn = ov * tanhf_acc(creg);

            g_hbuf[(t + 1) & 1][hofs] = hn;
            out[(size_t)t * (BATCH * HID) + hofs] = hn;
            if (write_hc && t == SEQLEN - 1) {
                out[(size_t)SEQLEN * BATCH * HID + hofs] = hn;
                out[(size_t)SEQLEN * BATCH * HID + BATCH * HID + hofs] = creg;
            }
        }

        __threadfence();
        __syncthreads();
        if (tid == 0) atomicExch((int*)&g_flags[bi][cj], t + 1);
    }
}

// =====================================================================================
extern "C" void kernel_launch(void* const* d_in, const int* in_sizes, int n_in,
                              void* d_out, int out_size)
{
    const float* input = (const float*)d_in[0];
    const float* h0    = (const float*)d_in[1];
    const float* c0    = (const float*)d_in[2];
    const float* Wih   = (const float*)d_in[3];
    const float* Whh   = (const float*)d_in[4];
    const float* bih   = (const float*)d_in[5];
    const float* bhh   = (const float*)d_in[6];
    (void)in_sizes; (void)n_in;

    float* out = (float*)d_out;
    const int n_outputs = SEQLEN * BATCH * HID;
    int write_hc = (out_size >= n_outputs + 2 * BATCH * HID) ? 1 : 0;

    static int configured = 0;
    if (!configured) {
        cudaFuncSetAttribute(gemm_hmma, cudaFuncAttributeMaxDynamicSharedMemorySize,
                             GEMM_SMEM);
        cudaFuncSetAttribute(lstm_rec, cudaFuncAttributeMaxDynamicSharedMemorySize,
                             REC_SMEM);
        configured = 1;
    }

    __nv_bfloat16 *ah, *al, *wh, *wl, *rh, *rl;
    cudaGetSymbolAddress((void**)&ah, g_Ah);
    cudaGetSymbolAddress((void**)&al, g_Al);
    cudaGetSymbolAddress((void**)&wh, g_Wh);
    cudaGetSymbolAddress((void**)&wl, g_Wl);
    cudaGetSymbolAddress((void**)&rh, g_Rh);
    cudaGetSymbolAddress((void**)&rl, g_Rl);

    conv_split<<<512, 256>>>(Wih, wh, wl, (G4 * INP) / 4);
    conv_split<<<512, 256>>>(Whh, rh, rl, (G4 * HID) / 4);
    conv_split<<<2048, 256>>>(input, ah, al, (MTOT * INP) / 4);
    gemm_hmma<<<dim3(G4 / 64, MTOT / 128), 256, GEMM_SMEM>>>(bih, bhh);
    lstm_rec<<<NB_REC, 512, REC_SMEM>>>(h0, c0, out, write_hc);
}

// round 10
// speedup vs baseline: 1.6498x; 1.0520x over previous
#include <cuda_runtime.h>
#include <cuda_bf16.h>
#include <cstdint>
#include <cstddef>

#define SEQLEN 512
#define BATCH  64
#define HID    512
#define INP    512
#define G4     2048
#define NB_REC 128
#define MTOT   (SEQLEN * BATCH)

// ---------------- device scratch ----------------
__device__ float g_xproj[(size_t)SEQLEN * BATCH * G4];
__device__ __align__(16) float g_hbuf[2][BATCH * HID];
__device__ int   g_flags[4][32];
__device__ __align__(256) __nv_bfloat16 g_Ah[(size_t)MTOT * INP];
__device__ __align__(256) __nv_bfloat16 g_Al[(size_t)MTOT * INP];
__device__ __align__(256) __nv_bfloat16 g_Wh[(size_t)G4 * INP];
__device__ __align__(256) __nv_bfloat16 g_Wl[(size_t)G4 * INP];
__device__ __align__(256) __nv_bfloat16 g_Rh[(size_t)G4 * HID];   // W_hh hi
__device__ __align__(256) __nv_bfloat16 g_Rl[(size_t)G4 * HID];   // W_hh lo

// ---------------- helpers ----------------
__device__ __forceinline__ float sigf(float x) { return 1.0f / (1.0f + __expf(-x)); }
__device__ __forceinline__ float tanhf_acc(float x) {
    return 2.0f / (1.0f + __expf(-2.0f * x)) - 1.0f;
}
__device__ __forceinline__ unsigned smem_u32(const void* p) {
    unsigned a;
    asm("{ .reg .u64 t; cvta.to.shared.u64 t, %1; cvt.u32.u64 %0, t; }" : "=r"(a) : "l"(p));
    return a;
}
__device__ __forceinline__ void cp16(unsigned dst, const void* src) {
    asm volatile("cp.async.cg.shared.global [%0], [%1], 16;" :: "r"(dst), "l"(src));
}
__device__ __forceinline__ unsigned lds32(unsigned addr) {
    unsigned v;
    asm("ld.shared.b32 %0, [%1];" : "=r"(v) : "r"(addr));
    return v;
}
__device__ __forceinline__ void mma_bf16(float* d, const unsigned* a, const unsigned* b) {
    asm("mma.sync.aligned.m16n8k16.row.col.f32.bf16.bf16.f32 "
        "{%0,%1,%2,%3}, {%4,%5,%6,%7}, {%8,%9}, {%0,%1,%2,%3};"
        : "+f"(d[0]), "+f"(d[1]), "+f"(d[2]), "+f"(d[3])
        : "r"(a[0]), "r"(a[1]), "r"(a[2]), "r"(a[3]), "r"(b[0]), "r"(b[1]));
}

// =====================================================================================
// fp32 -> bf16 hi/lo split. Block 0 also zeroes recurrence flags.
// =====================================================================================
__global__ void conv_split(const float* __restrict__ src, __nv_bfloat16* __restrict__ hi,
                           __nv_bfloat16* __restrict__ lo, int n4)
{
    if (blockIdx.x == 0 && threadIdx.x < 128) ((int*)g_flags)[threadIdx.x] = 0;
    int i = blockIdx.x * blockDim.x + threadIdx.x;
    int stride = gridDim.x * blockDim.x;
    for (; i < n4; i += stride) {
        float4 v = ((const float4*)src)[i];
        float f[4] = {v.x, v.y, v.z, v.w};
        unsigned hv0 = 0, hv1 = 0, lv0 = 0, lv1 = 0;
        #pragma unroll
        for (int j = 0; j < 4; j++) {
            __nv_bfloat16 h = __float2bfloat16(f[j]);
            __nv_bfloat16 l = __float2bfloat16(f[j] - __bfloat162float(h));
            unsigned hb = (unsigned)__bfloat16_as_ushort(h);
            unsigned lb = (unsigned)__bfloat16_as_ushort(l);
            if (j < 2) { hv0 |= hb << (16 * j);       lv0 |= lb << (16 * j); }
            else       { hv1 |= hb << (16 * (j - 2)); lv1 |= lb << (16 * (j - 2)); }
        }
        uint2 hh; hh.x = hv0; hh.y = hv1;
        uint2 ll; ll.x = lv0; ll.y = lv1;
        ((uint2*)hi)[i] = hh;
        ((uint2*)lo)[i] = ll;
    }
}

// =====================================================================================
// Kernel 1: xproj GEMM via mma.sync bf16 split — EXACT round-8/9 version (known good)
// =====================================================================================
#define KT 32
#define APLANE 10240
#define BPLANE 5120
#define STG_SZ (2 * APLANE + 2 * BPLANE)
#define GEMM_SMEM (2 * STG_SZ)

__global__ __launch_bounds__(256, 2)
void gemm_hmma(const float* __restrict__ bih, const float* __restrict__ bhh)
{
    extern __shared__ char smraw[];
    const unsigned SB = smem_u32(smraw);
    const int tid  = threadIdx.x;
    const int lane = tid & 31;
    const int wid  = tid >> 5;
    const int wm   = wid >> 1;
    const int wn   = wid & 1;
    const int g    = lane >> 2;
    const int t    = lane & 3;
    const int n0   = blockIdx.x * 64;
    const int m0   = blockIdx.y * 128;

    auto copy_tile = [&](int kt) {
        const unsigned sb = SB + (unsigned)(kt & 1) * STG_SZ;
        const int k0 = kt * KT;
        #pragma unroll
        for (int u = 0; u < 4; u++) {
            int idx = tid + u * 256;
            int plane = idx >> 9, r = (idx >> 2) & 127, ch = idx & 3;
            const __nv_bfloat16* src = (plane ? g_Al : g_Ah)
                                     + (size_t)(m0 + r) * INP + k0 + ch * 8;
            cp16(sb + (unsigned)(plane * APLANE + r * 80 + ch * 16), src);
        }
        #pragma unroll
        for (int u = 0; u < 2; u++) {
            int idx = tid + u * 256;
            int plane = (idx >> 8) & 1, r = (idx >> 2) & 63, ch = idx & 3;
            const __nv_bfloat16* src = (plane ? g_Wl : g_Wh)
                                     + (size_t)(n0 + r) * INP + k0 + ch * 8;
            cp16(sb + (unsigned)(2 * APLANE + plane * BPLANE + r * 80 + ch * 16), src);
        }
        asm volatile("cp.async.commit_group;");
    };

    float d[2][4][4];
    #pragma unroll
    for (int i = 0; i < 2; i++)
        #pragma unroll
        for (int j = 0; j < 4; j++)
            #pragma unroll
            for (int q = 0; q < 4; q++) d[i][j][q] = 0.f;

    copy_tile(0);
    copy_tile(1);

    for (int kt = 0; kt < 16; kt++) {
        if (kt < 15) asm volatile("cp.async.wait_group 1;" ::: "memory");
        else         asm volatile("cp.async.wait_group 0;" ::: "memory");
        __syncthreads();

        const unsigned sb = SB + (unsigned)(kt & 1) * STG_SZ;
        #pragma unroll
        for (int sub = 0; sub < 2; sub++) {
            const unsigned koff = (unsigned)(sub * 32 + t * 4);
            unsigned ah[2][4], al[2][4], bh[4][2], bl[4][2];
            #pragma unroll
            for (int i = 0; i < 2; i++) {
                unsigned b0 = sb + (unsigned)((wm * 32 + i * 16 + g) * 80) + koff;
                ah[i][0] = lds32(b0);            ah[i][2] = lds32(b0 + 16);
                ah[i][1] = lds32(b0 + 640);      ah[i][3] = lds32(b0 + 656);
                al[i][0] = lds32(b0 + APLANE);       al[i][2] = lds32(b0 + APLANE + 16);
                al[i][1] = lds32(b0 + APLANE + 640); al[i][3] = lds32(b0 + APLANE + 656);
            }
            #pragma unroll
            for (int j = 0; j < 4; j++) {
                unsigned b0 = sb + (unsigned)(2 * APLANE + (wn * 32 + j * 8 + g) * 80) + koff;
                bh[j][0] = lds32(b0);          bh[j][1] = lds32(b0 + 16);
                bl[j][0] = lds32(b0 + BPLANE); bl[j][1] = lds32(b0 + BPLANE + 16);
            }
            #pragma unroll
            for (int i = 0; i < 2; i++)
                #pragma unroll
                for (int j = 0; j < 4; j++) {
                    mma_bf16(d[i][j], ah[i], bh[j]);
                    mma_bf16(d[i][j], ah[i], bl[j]);
                    mma_bf16(d[i][j], al[i], bh[j]);
                }
        }
        __syncthreads();
        if (kt + 2 < 16) copy_tile(kt + 2);
    }

    #pragma unroll
    for (int j = 0; j < 4; j++) {
        int col = n0 + wn * 32 + j * 8 + t * 2;
        float b0 = bih[col] + bhh[col];
        float b1 = bih[col + 1] + bhh[col + 1];
        #pragma unroll
        for (int i = 0; i < 2; i++) {
            int row = m0 + wm * 32 + i * 16 + g;
            float2 v0; v0.x = d[i][j][0] + b0; v0.y = d[i][j][1] + b1;
            float2 v1; v1.x = d[i][j][2] + b0; v1.y = d[i][j][3] + b1;
            *(float2*)&g_xproj[(size_t)row * G4 + col] = v0;
            *(float2*)&g_xproj[(size_t)(row + 8) * G4 + col] = v1;
        }
    }
}

// =====================================================================================
// Kernel 2: persistent recurrence with HMMA. NEW phase-B tiling:
// 16 warps = 4 n-groups (16 gate rows = 2 B-tiles) x 4 k-quarters (128k = 8 k16).
// A fragments amortize over 2 B-tiles: 2048 LDS.32/CTA/step (was 4608).
// 3 split terms -> 3 independent accumulator sets (ILP). Everything else = round 9.
// =====================================================================================
#define SM_WH  0u
#define SM_WL  81920u
#define SM_HH  163840u
#define SM_HL  184320u
#define SM_RED 204800u
#define REC_SMEM (204800 + 4 * 1088 * 4)    // 222208

__global__ __launch_bounds__(512, 1)
void lstm_rec(const float* __restrict__ h0, const float* __restrict__ c0,
              float* __restrict__ out, int write_hc)
{
    extern __shared__ char sm[];
    const unsigned SB = smem_u32(sm);
    float* red = (float*)(sm + SM_RED);

    const int tid  = threadIdx.x;
    const int bi   = blockIdx.x >> 5;
    const int cj   = blockIdx.x & 31;
    const int lane = tid & 31;
    const int wid  = tid >> 5;
    const int nh   = wid & 3;           // n-group: 16 gate rows (2 B-tiles)
    const int kq   = wid >> 2;          // k-quarter: 128 k (8 k16 chunks)
    const int g    = lane >> 2;
    const int tq   = lane & 3;

    const int cb   = (tid & 255) >> 4;
    const int cjl  = tid & 15;
    const size_t hofs = (size_t)(bi * 16 + cb) * HID + cj * 16 + cjl;

    // ---- resident W_hh hi/lo: 64 rows x 512 k, tiled [kt][r][80B] (round-9 layout) ----
    for (int idx = tid; idx < 8192; idx += 512) {
        int plane = idx >> 12;
        int q = idx & 4095;
        int r = q >> 6, kt = (q >> 2) & 15, ch = q & 3;
        int ty = r >> 4, j = r & 15;
        const __nv_bfloat16* base = plane ? g_Rl : g_Rh;
        const __nv_bfloat16* src =
            base + (size_t)(ty * HID + cj * 16 + j) * HID + kt * 32 + ch * 8;
        cp16(SB + (plane ? SM_WL : SM_WH)
                + (unsigned)(kt * 5120 + r * 80 + ch * 16), src);
    }
    asm volatile("cp.async.commit_group;");
    asm volatile("cp.async.wait_group 0;" ::: "memory");
    float creg = (tid < 256) ? c0[hofs] : 0.0f;
    __syncthreads();

    volatile int* flags = (volatile int*)&g_flags[bi][0];

    // fragment base addresses (constant per thread)
    const unsigned aWH = SB + SM_WH + (unsigned)((nh * 16 + g) * 80 + tq * 4);
    const unsigned aWL = SB + SM_WL + (unsigned)((nh * 16 + g) * 80 + tq * 4);
    const unsigned aHH = SB + SM_HH + (unsigned)(g * 80 + tq * 4);
    const unsigned aHL = SB + SM_HL + (unsigned)(g * 80 + tq * 4);

    for (int t = 0; t < SEQLEN; t++) {
        // ---- prefetch x_proj gates ----
        float xg0 = 0.f, xg1 = 0.f, xg2 = 0.f, xg3 = 0.f;
        if (tid < 256) {
            size_t xofs = ((size_t)t * BATCH + bi * 16 + cb) * G4 + cj * 16 + cjl;
            xg0 = __ldcg(&g_xproj[xofs]);
            xg1 = __ldcg(&g_xproj[xofs + HID]);
            xg2 = __ldcg(&g_xproj[xofs + 2 * HID]);
            xg3 = __ldcg(&g_xproj[xofs + 3 * HID]);
        }

        // ---- wait for h_t producers ----
        if (t > 0) {
            if (tid < 32) { while (flags[tid] < t) { } }
            __threadfence();
        }
        __syncthreads();

        // ---- split h_t -> bf16 hi/lo smem ----
        const float* hrow = ((t == 0) ? h0 : g_hbuf[t & 1]) + (size_t)(bi * 16) * HID;
        #pragma unroll
        for (int u = 0; u < 8; u++) {
            int idx = tid + u * 512;
            int b = idx >> 8, p = idx & 255;
            float2 v = __ldcg((const float2*)(hrow + (size_t)b * HID + p * 2));
            __nv_bfloat16 hx = __float2bfloat16(v.x);
            __nv_bfloat16 hy = __float2bfloat16(v.y);
            float rx = v.x - __bfloat162float(hx);
            float ry = v.y - __bfloat162float(hy);
            __nv_bfloat16 lx = __float2bfloat16(rx);
            __nv_bfloat16 ly = __float2bfloat16(ry);
            unsigned hw = (unsigned)__bfloat16_as_ushort(hx)
                        | ((unsigned)__bfloat16_as_ushort(hy) << 16);
            unsigned lw = (unsigned)__bfloat16_as_ushort(lx)
                        | ((unsigned)__bfloat16_as_ushort(ly) << 16);
            unsigned off = (unsigned)((p >> 4) * 1280 + b * 80 + (p & 15) * 4);
            *(unsigned*)(sm + SM_HH + off) = hw;
            *(unsigned*)(sm + SM_HL + off) = lw;
        }
        __syncthreads();

        // ---- HMMA: warp (nh, kq): 8 k16 chunks x 2 B-tiles x 3 split terms ----
        float d0[2][4] = {{0,0,0,0},{0,0,0,0}};
        float d1[2][4] = {{0,0,0,0},{0,0,0,0}};
        float d2[2][4] = {{0,0,0,0},{0,0,0,0}};
        #pragma unroll
        for (int c = 0; c < 8; c++) {
            int k16 = kq * 8 + c;
            unsigned wo = (unsigned)((k16 >> 1) * 5120 + (k16 & 1) * 32);
            unsigned ho = (unsigned)((k16 >> 1) * 1280 + (k16 & 1) * 32);
            unsigned ah[4], al[4];
            ah[0] = lds32(aHH + ho);       ah[2] = lds32(aHH + ho + 16);
            ah[1] = lds32(aHH + ho + 640); ah[3] = lds32(aHH + ho + 656);
            al[0] = lds32(aHL + ho);       al[2] = lds32(aHL + ho + 16);
            al[1] = lds32(aHL + ho + 640); al[3] = lds32(aHL + ho + 656);
            #pragma unroll
            for (int jt = 0; jt < 2; jt++) {
                unsigned bh[2], bl[2];
                unsigned bo = wo + (unsigned)(jt * 640);
                bh[0] = lds32(aWH + bo);   bh[1] = lds32(aWH + bo + 16);
                bl[0] = lds32(aWL + bo);   bl[1] = lds32(aWL + bo + 16);
                mma_bf16(d0[jt], ah, bh);
                mma_bf16(d1[jt], ah, bl);
                mma_bf16(d2[jt], al, bh);
            }
        }
        // store partials: red[kq][n=64][b stride 17]
        #pragma unroll
        for (int jt = 0; jt < 2; jt++) {
            int n = nh * 16 + jt * 8 + tq * 2;
            int base = kq * 1088 + n * 17;
            red[base + g]          = d0[jt][0] + d1[jt][0] + d2[jt][0];
            red[base + 17 + g]     = d0[jt][1] + d1[jt][1] + d2[jt][1];
            red[base + g + 8]      = d0[jt][2] + d1[jt][2] + d2[jt][2];
            red[base + 17 + g + 8] = d0[jt][3] + d1[jt][3] + d2[jt][3];
        }
        __syncthreads();

        // ---- phase C: reduce 4 k-quarters, gates, update ----
        if (tid < 256) {
            float s[4];
            #pragma unroll
            for (int ty = 0; ty < 4; ty++) {
                int n = ty * 16 + cjl;
                float v = red[n * 17 + cb];
                #pragma unroll
                for (int kk = 1; kk < 4; kk++)
                    v += red[kk * 1088 + n * 17 + cb];
                s[ty] = v;
            }
            float iv = sigf(s[0] + xg0);
            float fv = sigf(s[1] + xg1);
            float gv = tanhf_acc(s[2] + xg2);
            float ov = sigf(s[3] + xg3);
            creg = fv * creg + iv * gv;
            float hn = ov * tanhf_acc(creg);

            g_hbuf[(t + 1) & 1][hofs] = hn;
            out[(size_t)t * (BATCH * HID) + hofs] = hn;
            if (write_hc && t == SEQLEN - 1) {
                out[(size_t)SEQLEN * BATCH * HID + hofs] = hn;
                out[(size_t)SEQLEN * BATCH * HID + BATCH * HID + hofs] = creg;
            }
        }

        __threadfence();
        __syncthreads();
        if (tid == 0) atomicExch((int*)&g_flags[bi][cj], t + 1);
    }
}

// =====================================================================================
extern "C" void kernel_launch(void* const* d_in, const int* in_sizes, int n_in,
                              void* d_out, int out_size)
{
    const float* input = (const float*)d_in[0];
    const float* h0    = (const float*)d_in[1];
    const float* c0    = (const float*)d_in[2];
    const float* Wih   = (const float*)d_in[3];
    const float* Whh   = (const float*)d_in[4];
    const float* bih   = (const float*)d_in[5];
    const float* bhh   = (const float*)d_in[6];
    (void)in_sizes; (void)n_in;

    float* out = (float*)d_out;
    const int n_outputs = SEQLEN * BATCH * HID;
    int write_hc = (out_size >= n_outputs + 2 * BATCH * HID) ? 1 : 0;

    static int configured = 0;
    if (!configured) {
        cudaFuncSetAttribute(gemm_hmma, cudaFuncAttributeMaxDynamicSharedMemorySize,
                             GEMM_SMEM);
        cudaFuncSetAttribute(lstm_rec, cudaFuncAttributeMaxDynamicSharedMemorySize,
                             REC_SMEM);
        configured = 1;
    }

    __nv_bfloat16 *ah, *al, *wh, *wl, *rh, *rl;
    cudaGetSymbolAddress((void**)&ah, g_Ah);
    cudaGetSymbolAddress((void**)&al, g_Al);
    cudaGetSymbolAddress((void**)&wh, g_Wh);
    cudaGetSymbolAddress((void**)&wl, g_Wl);
    cudaGetSymbolAddress((void**)&rh, g_Rh);
    cudaGetSymbolAddress((void**)&rl, g_Rl);

    conv_split<<<512, 256>>>(Wih, wh, wl, (G4 * INP) / 4);
    conv_split<<<512, 256>>>(Whh, rh, rl, (G4 * HID) / 4);
    conv_split<<<2048, 256>>>(input, ah, al, (MTOT * INP) / 4);
    gemm_hmma<<<dim3(G4 / 64, MTOT / 128), 256, GEMM_SMEM>>>(bih, bhh);
    lstm_rec<<<NB_REC, 512, REC_SMEM>>>(h0, c0, out, write_hc);
}

// round 11
// speedup vs baseline: 1.7549x; 1.0637x over previous
#include <cuda_runtime.h>
#include <cuda_bf16.h>
#include <cstdint>
#include <cstddef>

#define SEQLEN 512
#define BATCH  64
#define HID    512
#define INP    512
#define G4     2048
#define NB_REC 128
#define MTOT   (SEQLEN * BATCH)

// ---------------- device scratch ----------------
__device__ float g_xproj[(size_t)SEQLEN * BATCH * G4];
__device__ int   g_flags[4][32];
__device__ __align__(256) __nv_bfloat16 g_Ah[(size_t)MTOT * INP];
__device__ __align__(256) __nv_bfloat16 g_Al[(size_t)MTOT * INP];
__device__ __align__(256) __nv_bfloat16 g_Wh[(size_t)G4 * INP];
__device__ __align__(256) __nv_bfloat16 g_Wl[(size_t)G4 * INP];
__device__ __align__(256) __nv_bfloat16 g_Rh[(size_t)G4 * HID];
__device__ __align__(256) __nv_bfloat16 g_Rl[(size_t)G4 * HID];
// h exchange buffer: [buf][bi][plane][16 kt-slabs x 16 b x 80B], bf16 pair-packed words
__device__ __align__(256) unsigned g_hbf[2][4][2][5120];

// ---------------- helpers ----------------
__device__ __forceinline__ float sigf(float x) { return 1.0f / (1.0f + __expf(-x)); }
__device__ __forceinline__ float tanhf_acc(float x) {
    return 2.0f / (1.0f + __expf(-2.0f * x)) - 1.0f;
}
__device__ __forceinline__ unsigned smem_u32(const void* p) {
    unsigned a;
    asm("{ .reg .u64 t; cvta.to.shared.u64 t, %1; cvt.u32.u64 %0, t; }" : "=r"(a) : "l"(p));
    return a;
}
__device__ __forceinline__ void cp16(unsigned dst, const void* src) {
    asm volatile("cp.async.cg.shared.global [%0], [%1], 16;" :: "r"(dst), "l"(src));
}
__device__ __forceinline__ void ldsm4(unsigned* r, unsigned addr) {
    asm volatile("ldmatrix.sync.aligned.m8n8.x4.shared.b16 {%0,%1,%2,%3}, [%4];"
                 : "=r"(r[0]), "=r"(r[1]), "=r"(r[2]), "=r"(r[3]) : "r"(addr));
}
__device__ __forceinline__ void mma_bf16(float* d, const unsigned* a, const unsigned* b) {
    asm("mma.sync.aligned.m16n8k16.row.col.f32.bf16.bf16.f32 "
        "{%0,%1,%2,%3}, {%4,%5,%6,%7}, {%8,%9}, {%0,%1,%2,%3};"
        : "+f"(d[0]), "+f"(d[1]), "+f"(d[2]), "+f"(d[3])
        : "r"(a[0]), "r"(a[1]), "r"(a[2]), "r"(a[3]), "r"(b[0]), "r"(b[1]));
}

// =====================================================================================
// fp32 -> bf16 hi/lo split. Block 0 also zeroes recurrence flags.
// =====================================================================================
__global__ void conv_split(const float* __restrict__ src, __nv_bfloat16* __restrict__ hi,
                           __nv_bfloat16* __restrict__ lo, int n4)
{
    if (blockIdx.x == 0 && threadIdx.x < 128) ((int*)g_flags)[threadIdx.x] = 0;
    int i = blockIdx.x * blockDim.x + threadIdx.x;
    int stride = gridDim.x * blockDim.x;
    for (; i < n4; i += stride) {
        float4 v = ((const float4*)src)[i];
        float f[4] = {v.x, v.y, v.z, v.w};
        unsigned hv0 = 0, hv1 = 0, lv0 = 0, lv1 = 0;
        #pragma unroll
        for (int j = 0; j < 4; j++) {
            __nv_bfloat16 h = __float2bfloat16(f[j]);
            __nv_bfloat16 l = __float2bfloat16(f[j] - __bfloat162float(h));
            unsigned hb = (unsigned)__bfloat16_as_ushort(h);
            unsigned lb = (unsigned)__bfloat16_as_ushort(l);
            if (j < 2) { hv0 |= hb << (16 * j);       lv0 |= lb << (16 * j); }
            else       { hv1 |= hb << (16 * (j - 2)); lv1 |= lb << (16 * (j - 2)); }
        }
        uint2 hh; hh.x = hv0; hh.y = hv1;
        uint2 ll; ll.x = lv0; ll.y = lv1;
        ((uint2*)hi)[i] = hh;
        ((uint2*)lo)[i] = ll;
    }
}

// =====================================================================================
// Kernel 1: xproj GEMM — round-8 structure, fragment loads via ldmatrix.x4.
// =====================================================================================
#define KT 32
#define APLANE 10240
#define BPLANE 5120
#define STG_SZ (2 * APLANE + 2 * BPLANE)
#define GEMM_SMEM (2 * STG_SZ)

__global__ __launch_bounds__(256, 2)
void gemm_hmma(const float* __restrict__ bih, const float* __restrict__ bhh)
{
    extern __shared__ char smraw[];
    const unsigned SB = smem_u32(smraw);
    const int tid  = threadIdx.x;
    const int lane = tid & 31;
    const int wid  = tid >> 5;
    const int wm   = wid >> 1;
    const int wn   = wid & 1;
    const int g    = lane >> 2;
    const int t    = lane & 3;
    const int n0   = blockIdx.x * 64;
    const int m0   = blockIdx.y * 128;

    // ldmatrix per-lane row selectors
    const unsigned rA = (unsigned)(lane & 15);            // A: 16 rows, k-half by lane>>4
    const unsigned kA = (unsigned)((lane >> 4) * 16);
    const unsigned rB = (unsigned)(((lane >> 4) << 3) | (lane & 7));  // B: 2 tiles x 8 rows
    const unsigned kB = (unsigned)(((lane >> 3) & 1) * 16);

    auto copy_tile = [&](int kt) {
        const unsigned sb = SB + (unsigned)(kt & 1) * STG_SZ;
        const int k0 = kt * KT;
        #pragma unroll
        for (int u = 0; u < 4; u++) {
            int idx = tid + u * 256;
            int plane = idx >> 9, r = (idx >> 2) & 127, ch = idx & 3;
            const __nv_bfloat16* src = (plane ? g_Al : g_Ah)
                                     + (size_t)(m0 + r) * INP + k0 + ch * 8;
            cp16(sb + (unsigned)(plane * APLANE + r * 80 + ch * 16), src);
        }
        #pragma unroll
        for (int u = 0; u < 2; u++) {
            int idx = tid + u * 256;
            int plane = (idx >> 8) & 1, r = (idx >> 2) & 63, ch = idx & 3;
            const __nv_bfloat16* src = (plane ? g_Wl : g_Wh)
                                     + (size_t)(n0 + r) * INP + k0 + ch * 8;
            cp16(sb + (unsigned)(2 * APLANE + plane * BPLANE + r * 80 + ch * 16), src);
        }
        asm volatile("cp.async.commit_group;");
    };

    float d[2][4][4];
    #pragma unroll
    for (int i = 0; i < 2; i++)
        #pragma unroll
        for (int j = 0; j < 4; j++)
            #pragma unroll
            for (int q = 0; q < 4; q++) d[i][j][q] = 0.f;

    copy_tile(0);
    copy_tile(1);

    for (int kt = 0; kt < 16; kt++) {
        if (kt < 15) asm volatile("cp.async.wait_group 1;" ::: "memory");
        else         asm volatile("cp.async.wait_group 0;" ::: "memory");
        __syncthreads();

        const unsigned sb = SB + (unsigned)(kt & 1) * STG_SZ;
        #pragma unroll
        for (int sub = 0; sub < 2; sub++) {
            const unsigned ko = (unsigned)(sub * 32);
            unsigned ah[2][4], al[2][4], bh4[2][4], bl4[2][4];
            #pragma unroll
            for (int i = 0; i < 2; i++) {
                unsigned ra = sb + (unsigned)((wm * 32 + i * 16 + rA) * 80) + ko + kA;
                ldsm4(ah[i], ra);
                ldsm4(al[i], ra + APLANE);
            }
            #pragma unroll
            for (int jp = 0; jp < 2; jp++) {
                unsigned rb = sb + 2 * APLANE
                            + (unsigned)((wn * 32 + jp * 16 + rB) * 80) + ko + kB;
                ldsm4(bh4[jp], rb);
                ldsm4(bl4[jp], rb + BPLANE);
            }
            #pragma unroll
            for (int i = 0; i < 2; i++)
                #pragma unroll
                for (int j = 0; j < 4; j++) {
                    const unsigned* bh = &bh4[j >> 1][(j & 1) * 2];
                    const unsigned* bl = &bl4[j >> 1][(j & 1) * 2];
                    mma_bf16(d[i][j], ah[i], bh);
                    mma_bf16(d[i][j], ah[i], bl);
                    mma_bf16(d[i][j], al[i], bh);
                }
        }
        __syncthreads();
        if (kt + 2 < 16) copy_tile(kt + 2);
    }

    #pragma unroll
    for (int j = 0; j < 4; j++) {
        int col = n0 + wn * 32 + j * 8 + t * 2;
        float b0 = bih[col] + bhh[col];
        float b1 = bih[col + 1] + bhh[col + 1];
        #pragma unroll
        for (int i = 0; i < 2; i++) {
            int row = m0 + wm * 32 + i * 16 + g;
            float2 v0; v0.x = d[i][j][0] + b0; v0.y = d[i][j][1] + b1;
            float2 v1; v1.x = d[i][j][2] + b0; v1.y = d[i][j][3] + b1;
            *(float2*)&g_xproj[(size_t)row * G4 + col] = v0;
            *(float2*)&g_xproj[(size_t)(row + 8) * G4 + col] = v1;
        }
    }
}

// =====================================================================================
// Kernel 2: persistent recurrence. h exchanged as bf16 hi/lo in consumer tile layout
// (producer-converted); staging via cp.async; ldmatrix fragment loads.
// Flags: value = number of published h versions (init h0 publish = 1; step t -> t+2).
// =====================================================================================
#define SM_WH  0u
#define SM_WL  81920u
#define SM_HH  163840u
#define SM_HL  184320u
#define SM_RED 204800u
#define REC_SMEM (204800 + 4 * 1088 * 4)    // 222208

__global__ __launch_bounds__(512, 1)
void lstm_rec(const float* __restrict__ h0, const float* __restrict__ c0,
              float* __restrict__ out, int write_hc)
{
    extern __shared__ char sm[];
    const unsigned SB = smem_u32(sm);
    float* red = (float*)(sm + SM_RED);

    const int tid  = threadIdx.x;
    const int bi   = blockIdx.x >> 5;
    const int cj   = blockIdx.x & 31;
    const int lane = tid & 31;
    const int wid  = tid >> 5;
    const int nh   = wid & 3;
    const int kq   = wid >> 2;

    const unsigned rA = (unsigned)(lane & 15);
    const unsigned kA = (unsigned)((lane >> 4) * 16);
    const unsigned rB = (unsigned)(((lane >> 4) << 3) | (lane & 7));
    const unsigned kB = (unsigned)(((lane >> 3) & 1) * 16);

    const int cb   = (tid & 255) >> 4;
    const int cjl  = tid & 15;
    const size_t hofs = (size_t)(bi * 16 + cb) * HID + cj * 16 + cjl;
    // producer word slot within a plane (pair-packed): p = global k-pair index
    const int pp   = cj * 8 + (cjl >> 1);
    const int wslot = (pp >> 4) * 320 + cb * 20 + (pp & 15);

    // ---- resident W_hh hi/lo (round-9 tiled layout) ----
    for (int idx = tid; idx < 8192; idx += 512) {
        int plane = idx >> 12;
        int q = idx & 4095;
        int r = q >> 6, kt = (q >> 2) & 15, ch = q & 3;
        int ty = r >> 4, j = r & 15;
        const __nv_bfloat16* base = plane ? g_Rl : g_Rh;
        const __nv_bfloat16* src =
            base + (size_t)(ty * HID + cj * 16 + j) * HID + kt * 32 + ch * 8;
        cp16(SB + (plane ? SM_WL : SM_WH)
                + (unsigned)(kt * 5120 + r * 80 + ch * 16), src);
    }
    asm volatile("cp.async.commit_group;");

    // ---- init-publish h0 slice (version 0 -> buf 0) ----
    if (tid < 256) {
        float hv = h0[hofs];
        __nv_bfloat16 hb = __float2bfloat16(hv);
        unsigned hu = (unsigned)__bfloat16_as_ushort(hb);
        unsigned lu = (unsigned)__bfloat16_as_ushort(
                          __float2bfloat16(hv - __bfloat162float(hb)));
        unsigned hn2 = __shfl_down_sync(0xffffffffu, hu, 1);
        unsigned ln2 = __shfl_down_sync(0xffffffffu, lu, 1);
        if (!(cjl & 1)) {
            g_hbf[0][bi][0][wslot] = hu | (hn2 << 16);
            g_hbf[0][bi][1][wslot] = lu | (ln2 << 16);
        }
    }
    __threadfence();
    __syncthreads();
    if (tid == 0) atomicExch(&g_flags[bi][cj], 1);

    asm volatile("cp.async.wait_group 0;" ::: "memory");
    float creg = (tid < 256) ? c0[hofs] : 0.0f;
    __syncthreads();

    volatile int* flags = (volatile int*)&g_flags[bi][0];

    for (int t = 0; t < SEQLEN; t++) {
        // ---- prefetch x_proj gates ----
        float xg0 = 0.f, xg1 = 0.f, xg2 = 0.f, xg3 = 0.f;
        if (tid < 256) {
            size_t xofs = ((size_t)t * BATCH + bi * 16 + cb) * G4 + cj * 16 + cjl;
            xg0 = __ldcg(&g_xproj[xofs]);
            xg1 = __ldcg(&g_xproj[xofs + HID]);
            xg2 = __ldcg(&g_xproj[xofs + 2 * HID]);
            xg3 = __ldcg(&g_xproj[xofs + 3 * HID]);
        }

        // ---- wait for version t from all 32 producers of this bi group ----
        if (tid < 32) { while (flags[tid] < t + 1) { } }
        __threadfence();
        __syncthreads();

        // ---- stage h_t (bf16 hi/lo, already tiled): 2 x 20480B via cp.async ----
        const char* hsrc = (const char*)&g_hbf[t & 1][bi][0][0];
        #pragma unroll
        for (int u = 0; u < 5; u++) {
            int idx = tid + u * 512;            // 0..2559
            int plane = idx >= 1280;
            unsigned off = (unsigned)((idx - plane * 1280) * 16);
            cp16(SB + (plane ? SM_HL : SM_HH) + off, hsrc + plane * 20480 + off);
        }
        asm volatile("cp.async.commit_group;");
        asm volatile("cp.async.wait_group 0;" ::: "memory");
        __syncthreads();

        // ---- HMMA: warp (nh, kq): 8 k16 chunks x 2 B-tiles x 3 split terms ----
        float d0[2][4] = {{0,0,0,0},{0,0,0,0}};
        float d1[2][4] = {{0,0,0,0},{0,0,0,0}};
        float d2[2][4] = {{0,0,0,0},{0,0,0,0}};
        #pragma unroll
        for (int c = 0; c < 8; c++) {
            int k16 = kq * 8 + c;
            unsigned hOff = (unsigned)((k16 >> 1) * 1280 + (k16 & 1) * 32);
            unsigned wOff = (unsigned)((k16 >> 1) * 5120 + (k16 & 1) * 32);
            unsigned ah4[4], al4[4], wh4[4], wl4[4];
            ldsm4(ah4, SB + SM_HH + hOff + rA * 80 + kA);
            ldsm4(al4, SB + SM_HL + hOff + rA * 80 + kA);
            ldsm4(wh4, SB + SM_WH + wOff + (unsigned)((nh * 16 + rB) * 80) + kB);
            ldsm4(wl4, SB + SM_WL + wOff + (unsigned)((nh * 16 + rB) * 80) + kB);
            #pragma unroll
            for (int jt = 0; jt < 2; jt++) {
                mma_bf16(d0[jt], ah4, &wh4[jt * 2]);
                mma_bf16(d1[jt], ah4, &wl4[jt * 2]);
                mma_bf16(d2[jt], al4, &wh4[jt * 2]);
            }
        }
        {
            const int g = lane >> 2, tq = lane & 3;
            #pragma unroll
            for (int jt = 0; jt < 2; jt++) {
                int n = nh * 16 + jt * 8 + tq * 2;
                int base = kq * 1088 + n * 17;
                red[base + g]          = d0[jt][0] + d1[jt][0] + d2[jt][0];
                red[base + 17 + g]     = d0[jt][1] + d1[jt][1] + d2[jt][1];
                red[base + g + 8]      = d0[jt][2] + d1[jt][2] + d2[jt][2];
                red[base + 17 + g + 8] = d0[jt][3] + d1[jt][3] + d2[jt][3];
            }
        }
        __syncthreads();

        // ---- phase C: reduce, gates, produce + publish h_{t+1} ----
        float hn = 0.f;
        if (tid < 256) {
            float s[4];
            #pragma unroll
            for (int ty = 0; ty < 4; ty++) {
                int n = ty * 16 + cjl;
                float v = red[n * 17 + cb];
                #pragma unroll
                for (int kk = 1; kk < 4; kk++)
                    v += red[kk * 1088 + n * 17 + cb];
                s[ty] = v;
            }
            float iv = sigf(s[0] + xg0);
            float fv = sigf(s[1] + xg1);
            float gv = tanhf_acc(s[2] + xg2);
            float ov = sigf(s[3] + xg3);
            creg = fv * creg + iv * gv;
            hn = ov * tanhf_acc(creg);

            __nv_bfloat16 hb = __float2bfloat16(hn);
            unsigned hu = (unsigned)__bfloat16_as_ushort(hb);
            unsigned lu = (unsigned)__bfloat16_as_ushort(
                              __float2bfloat16(hn - __bfloat162float(hb)));
            unsigned hn2 = __shfl_down_sync(0xffffffffu, hu, 1);
            unsigned ln2 = __shfl_down_sync(0xffffffffu, lu, 1);
            if (!(cjl & 1)) {
                g_hbf[(t + 1) & 1][bi][0][wslot] = hu | (hn2 << 16);
                g_hbf[(t + 1) & 1][bi][1][wslot] = lu | (ln2 << 16);
            }
        }

        __threadfence();
        __syncthreads();
        if (tid == 0) atomicExch(&g_flags[bi][cj], t + 2);

        // ---- out stores off the publish path ----
        if (tid < 256) {
            out[(size_t)t * (BATCH * HID) + hofs] = hn;
            if (write_hc && t == SEQLEN - 1) {
                out[(size_t)SEQLEN * BATCH * HID + hofs] = hn;
                out[(size_t)SEQLEN * BATCH * HID + BATCH * HID + hofs] = creg;
            }
        }
    }
}

// =====================================================================================
extern "C" void kernel_launch(void* const* d_in, const int* in_sizes, int n_in,
                              void* d_out, int out_size)
{
    const float* input = (const float*)d_in[0];
    const float* h0    = (const float*)d_in[1];
    const float* c0    = (const float*)d_in[2];
    const float* Wih   = (const float*)d_in[3];
    const float* Whh   = (const float*)d_in[4];
    const float* bih   = (const float*)d_in[5];
    const float* bhh   = (const float*)d_in[6];
    (void)in_sizes; (void)n_in;

    float* out = (float*)d_out;
    const int n_outputs = SEQLEN * BATCH * HID;
    int write_hc = (out_size >= n_outputs + 2 * BATCH * HID) ? 1 : 0;

    static int configured = 0;
    if (!configured) {
        cudaFuncSetAttribute(gemm_hmma, cudaFuncAttributeMaxDynamicSharedMemorySize,
                             GEMM_SMEM);
        cudaFuncSetAttribute(lstm_rec, cudaFuncAttributeMaxDynamicSharedMemorySize,
                             REC_SMEM);
        configured = 1;
    }

    __nv_bfloat16 *ah, *al, *wh, *wl, *rh, *rl;
    cudaGetSymbolAddress((void**)&ah, g_Ah);
    cudaGetSymbolAddress((void**)&al, g_Al);
    cudaGetSymbolAddress((void**)&wh, g_Wh);
    cudaGetSymbolAddress((void**)&wl, g_Wl);
    cudaGetSymbolAddress((void**)&rh, g_Rh);
    cudaGetSymbolAddress((void**)&rl, g_Rl);

    conv_split<<<512, 256>>>(Wih, wh, wl, (G4 * INP) / 4);
    conv_split<<<512, 256>>>(Whh, rh, rl, (G4 * HID) / 4);
    conv_split<<<2048, 256>>>(input, ah, al, (MTOT * INP) / 4);
    gemm_hmma<<<dim3(G4 / 64, MTOT / 128), 256, GEMM_SMEM>>>(bih, bhh);
    lstm_rec<<<NB_REC, 512, REC_SMEM>>>(h0, c0, out, write_hc);
}